// round 14
// baseline (speedup 1.0000x reference)
#include <cuda_runtime.h>
#include <float.h>

#define B_IMG 2
#define N_BOX 20000
#define C_CLS 80
#define BC (B_IMG * C_CLS)          // 160
#define CAP 1024                    // global candidate cap per (b,c)
#define CPAD 32                     // counter padding (128B stride)
#define MAXV 512                    // fast-path NMS limit (== TPB); slow fallback beyond
#define WMAX (MAXV / 32)            // 16
#define PRE_K 1000
#define MAX_DET 300
#define SCORE_THR 0.05f
#define IOU_THR 0.5f
#define WIN 16
#define NB 2048
#define CCAP 2048
#define GRID 160
#define TPB 512
#define NWARP (TPB / 32)
#define BATCH 10
#define SMEM_BYTES 67584

// ---------------- scratch (no allocations allowed) ----------------
__device__ int   g_b1, g_done, g_done2;      // barrier + finisher tickets (start 0, self-reset)
__device__ int   g_cand_count[BC * CPAD];
__device__ float g_cand_score[BC * CAP];
__device__ int   g_cand_idx[BC * CAP];
__device__ int   g_keep_count[BC];
__device__ float g_keep_score[BC * MAX_DET];
__device__ int   g_keep_idx[BC * MAX_DET];

// ---- smem bitonic (slow fallback only) ----
__device__ __forceinline__ void bitonic_desc(unsigned long long* sk, int M, int tid) {
    for (int k = 2; k <= M; k <<= 1) {
        for (int j = k >> 1; j > 0; j >>= 1) {
            for (int i = tid; i < M; i += TPB) {
                int ixj = i ^ j;
                if (ixj > i) {
                    unsigned long long a = sk[i], d = sk[ixj];
                    bool up = ((i & k) == 0);
                    if (up ? (a < d) : (a > d)) { sk[i] = d; sk[ixj] = a; }
                }
            }
            __syncthreads();
        }
    }
}

// ---- 2-barrier bucket finder ----
__device__ __forceinline__ void find_cross(const int* hist, int nb, int rem,
                                           int tid, int* warp_tot, int* res) {
    int chunk = nb / TPB;
    int base = tid * chunk;
    int lsum = 0;
    for (int k = 0; k < chunk; k++) lsum += hist[base + k];

    int lane = tid & 31, wid = tid >> 5;
    int suff = lsum;
    #pragma unroll
    for (int off = 1; off < 32; off <<= 1) {
        int v = __shfl_down_sync(0xffffffffu, suff, off);
        if (lane + off < 32) suff += v;
    }
    if (lane == 0) warp_tot[wid] = suff;
    __syncthreads();

    int after_w = 0, total = 0;
    #pragma unroll
    for (int w = 0; w < NWARP; w++) {
        int wt = warp_tot[w];
        total += wt;
        if (w > wid) after_w += wt;
    }
    int incl = after_w + suff;
    int after_c = incl - lsum;
    if (tid == 0 && total < rem) { res[0] = -1; res[1] = total; }
    if (total >= rem && after_c < rem && rem <= incl) {
        int cum = after_c;
        for (int k = chunk - 1; k >= 0; k--) {
            int h = hist[base + k];
            cum += h;
            if (cum >= rem) { res[0] = base + k; res[1] = cum - h; break; }
        }
    }
}

__global__ __launch_bounds__(TPB)
void fused_kernel(const float* __restrict__ boxes,
                  const float4* __restrict__ cls4,
                  const float* __restrict__ cen,
                  float* __restrict__ out) {
    extern __shared__ unsigned char dynbuf[];
    // phase-2 layout
    unsigned long long* s_key  = (unsigned long long*)dynbuf;            // CAP (8KB)
    float4*             s_box  = (float4*)(dynbuf + 8192);               // MAXV (8KB)
    unsigned long long* s_xkey = (unsigned long long*)(dynbuf + 16384);  // MAXV (4KB)
    float*              sx1    = (float*)(dynbuf + 20480);               // MAXV (2KB)
    float4*             s_f4   = (float4*)(dynbuf + 22528);              // MAXV (8KB)
    int*                srank  = (int*)(dynbuf + 30720);                 // MAXV (2KB)
    unsigned*           s_mask = (unsigned*)(dynbuf + 32768);            // MAXV*WMAX (32KB)
    unsigned*           s_anyw = (unsigned*)(dynbuf + 65536);            // WMAX words
    __shared__ int s_ticket;

    const int tid = threadIdx.x;
    const int bc  = blockIdx.x;
    const int b   = bc / C_CLS;

    // ===== phase 1: coalesced threshold + compact (batched loads) =====
    {
        const int total4 = B_IMG * N_BOX * C_CLS / 4;     // 800000
        const int start  = bc * TPB + tid;
        const int stride = GRID * TPB;                    // 81920

        float4 vbuf[BATCH];
        float  cbuf[BATCH];
        #pragma unroll
        for (int k = 0; k < BATCH; k++) {
            int q = start + k * stride;
            if (q < total4) {
                vbuf[k] = cls4[q];
                cbuf[k] = cen[q / 20];    // q/20 == b*N_BOX+n (80%4==0)
            }
        }
        #pragma unroll
        for (int k = 0; k < BATCH; k++) {
            int q = start + k * stride;
            if (q < total4) {
                float4 v = vbuf[k];
                if (v.x > SCORE_THR || v.y > SCORE_THR || v.z > SCORE_THR || v.w > SCORE_THR) {
                    int base = q * 4;
                    int c0  = base % C_CLS;
                    int rem = q / 20;
                    int bb  = rem / N_BOX;
                    float ce = cbuf[k];
                    float vv[4] = {v.x, v.y, v.z, v.w};
                    #pragma unroll
                    for (int e = 0; e < 4; e++) {
                        if (vv[e] > SCORE_THR) {
                            float s = sqrtf(vv[e] * ce);
                            int idx = bb * C_CLS + c0 + e;
                            int pos = atomicAdd(&g_cand_count[idx * CPAD], 1);
                            if (pos < CAP) {
                                g_cand_score[idx * CAP + pos] = s;
                                g_cand_idx[idx * CAP + pos]   = rem % N_BOX;
                            }
                        }
                    }
                }
            }
        }
    }

    // ---- grid barrier 1 ----
    __threadfence();
    __syncthreads();
    if (tid == 0) {
        atomicAdd(&g_b1, 1);
        while (*(volatile int*)&g_b1 < GRID) {}
    }
    __syncthreads();
    __threadfence();

    // ===== phase 2: score rank-sort + x-sweep NMS =====
    int V = g_cand_count[bc * CPAD];
    if (V > CAP) V = CAP;
    {
        int M = 1;
        while (M < V) M <<= 1;

        for (int i = tid; i < M; i += TPB) {
            if (i < V) {
                unsigned sb = __float_as_uint(g_cand_score[bc * CAP + i]);
                unsigned ix = (unsigned)g_cand_idx[bc * CAP + i];
                s_key[i] = ((unsigned long long)sb << 32) | (unsigned)(~ix);
            } else {
                s_key[i] = 0ull;
            }
        }
        __syncthreads();
        if (tid == 0) g_cand_count[bc * CPAD] = 0;   // re-zero for next replay (after sync: safe)

        int K_eff = V < PRE_K ? V : PRE_K;

        if (V <= MAXV) {
            // ---- rank-sort by score key (unique keys), in-place scatter ----
            unsigned long long mykey = (tid < V) ? s_key[tid] : 0ull;
            int rank = 0;
            for (int j = 0; j < V; j++) rank += (s_key[j] > mykey);
            __syncthreads();
            if (tid < V) s_key[rank] = mykey;
            __syncthreads();

            // gather boxes in score order; zero masks
            for (int i = tid; i < V; i += TPB) {
                int n = (int)(~((unsigned)s_key[i]));
                s_box[i] = reinterpret_cast<const float4*>(boxes)[b * N_BOX + n];
            }
            for (int t = tid; t < V * WMAX; t += TPB) s_mask[t] = 0u;
            if (tid < WMAX) s_anyw[tid] = 0u;
            __syncthreads();

            // ---- rank-sort by x1 ascending (key = ~x1bits<<32 | scorerank) ----
            unsigned long long xkey = (tid < V)
                ? ((unsigned long long)(~__float_as_uint(s_box[tid].x)) << 32) | (unsigned)tid
                : 0ull;
            if (tid < V) s_xkey[tid] = xkey;
            __syncthreads();
            int xrank = 0;
            for (int j = 0; j < V; j++) xrank += (s_xkey[j] > xkey);
            __syncthreads();
            if (tid < V) s_xkey[xrank] = xkey;
            __syncthreads();

            // build x-order SoA
            for (int p = tid; p < V; p += TPB) {
                int r = (int)(unsigned)s_xkey[p];
                float4 bb4 = s_box[r];
                sx1[p] = bb4.x;
                s_f4[p] = make_float4(bb4.z, bb4.y, bb4.w,
                                      (bb4.z - bb4.x) * (bb4.w - bb4.y));
                srank[p] = r;
            }
            __syncthreads();

            // pair sweep: q>p overlaps in x iff x1_q < x2_p (x1 ascending)
            for (int p = tid; p < V; p += TPB) {
                float4 fp = s_f4[p];                // (x2, y1, y2, area)
                float x2p = fp.x, y1p = fp.y, y2p = fp.z, arp = fp.w;
                int rp = srank[p];
                for (int q = p + 1; q < V; q++) {
                    float x1q = sx1[q];
                    if (x1q >= x2p) break;
                    float4 fq = s_f4[q];
                    float w_ = fminf(x2p, fq.x) - x1q;
                    float h_ = fminf(y2p, fq.z) - fmaxf(y1p, fq.y);
                    if (h_ > 0.0f) {
                        float inter = w_ * h_;
                        float uni = arp + fq.w - inter;
                        if (inter / fmaxf(uni, 1e-8f) > IOU_THR) {
                            int rq = srank[q];
                            int imin = rp < rq ? rp : rq;
                            int jmax = rp < rq ? rq : rp;
                            atomicOr(&s_mask[imin * WMAX + (jmax >> 5)], 1u << (jmax & 31));
                            atomicOr(&s_anyw[imin >> 5], 1u << (imin & 31));
                        }
                    }
                }
            }
            __syncthreads();

            // chunked serial greedy sweep (warp 0); suppression-sparse fast path
            if (tid < 32) {
                int W = (K_eff + 31) >> 5;
                unsigned sup  = 0;
                unsigned anyw = (tid < WMAX) ? s_anyw[tid] : 0u;
                int nk = 0;
                int nchunk = (K_eff + 31) >> 5;
                for (int g = 0; g < nchunk && nk < MAX_DET; g++) {
                    unsigned ow = __shfl_sync(0xffffffffu, sup,  g);
                    unsigned ag = __shfl_sync(0xffffffffu, anyw, g);
                    int bend = min(32, K_eff - (g << 5));
                    for (int bb2 = 0; bb2 < bend; bb2++) {
                        if (!(ow & (1u << bb2))) {
                            int i = (g << 5) + bb2;
                            if (tid == 0) {
                                unsigned long long kk = s_key[i];
                                g_keep_score[bc * MAX_DET + nk] = __uint_as_float((unsigned)(kk >> 32));
                                g_keep_idx[bc * MAX_DET + nk]   = (int)(~((unsigned)kk));
                            }
                            nk++;
                            if ((ag >> bb2) & 1u) {     // warp-uniform: row i suppresses someone
                                unsigned m = (tid < W) ? s_mask[i * WMAX + tid] : 0u;
                                sup |= m;
                                ow  |= __shfl_sync(0xffffffffu, m, g);
                            }
                            if (nk >= MAX_DET) break;
                        }
                    }
                }
                if (tid == 0) g_keep_count[bc] = nk;
            }
        } else {
            // slow fallback: full bitonic + barrier greedy, boxes from global
            bitonic_desc(s_key, M, tid);
            unsigned char* sup = (unsigned char*)s_mask;
            __shared__ int s_nk;
            for (int i = tid; i < K_eff; i += TPB) sup[i] = 0;
            if (tid == 0) s_nk = 0;
            __syncthreads();
            for (int i = 0; i < K_eff; i++) {
                if (!sup[i]) {
                    unsigned long long ki = s_key[i];
                    int ni = (int)(~((unsigned)ki));
                    if (tid == 0) {
                        int nk = s_nk;
                        g_keep_score[bc * MAX_DET + nk] = __uint_as_float((unsigned)(ki >> 32));
                        g_keep_idx[bc * MAX_DET + nk]   = ni;
                        s_nk = nk + 1;
                    }
                    float4 bi = reinterpret_cast<const float4*>(boxes)[b * N_BOX + ni];
                    float ai = (bi.z - bi.x) * (bi.w - bi.y);
                    for (int j = i + 1 + tid; j < K_eff; j += TPB) {
                        if (!sup[j]) {
                            int nj = (int)(~((unsigned)s_key[j]));
                            float4 bj = reinterpret_cast<const float4*>(boxes)[b * N_BOX + nj];
                            float aj = (bj.z - bj.x) * (bj.w - bj.y);
                            float w_ = fmaxf(fminf(bi.z, bj.z) - fmaxf(bi.x, bj.x), 0.0f);
                            float h_ = fmaxf(fminf(bi.w, bj.w) - fmaxf(bi.y, bj.y), 0.0f);
                            float inter = w_ * h_;
                            float uni = ai + aj - inter;
                            if (inter / fmaxf(uni, 1e-8f) > IOU_THR) sup[j] = 1;
                        }
                    }
                    __syncthreads();
                    if (s_nk >= MAX_DET) break;
                }
            }
            if (tid == 0) g_keep_count[bc] = (s_nk <= MAX_DET) ? s_nk : MAX_DET;
        }
    }

    // ===== finisher ticket: last B_IMG finishers run the merge =====
    __threadfence();
    __syncthreads();
    if (tid == 0) s_ticket = atomicAdd(&g_done, 1);
    __syncthreads();
    int ticket = s_ticket;
    if (ticket < GRID - B_IMG) return;
    const int img = ticket - (GRID - B_IMG);
    if (tid == 0) {
        while (*(volatile int*)&g_done < GRID) {}
        int r = atomicAdd(&g_done2, 1);
        if (r == B_IMG - 1) { g_done = 0; g_done2 = 0; g_b1 = 0; }   // reset for replay
    }
    __syncthreads();
    __threadfence();

    // ===== phase 3: per-image top-300 (WIN=16, 1-pass bucket select + rank-scatter) =====
    {
        unsigned* s_u    = (unsigned*)dynbuf;                         // C_CLS*WIN = 1280
        int*      hist   = (int*)(s_u + C_CLS * WIN);                 // NB (8KB)
        int*      wtot   = hist + NB;                                 // pad 64
        int*      s_ccnt = wtot + 64;                                 // C_CLS
        unsigned long long* s_k3 = (unsigned long long*)(s_ccnt + C_CLS + 2); // CCAP (16KB)
        unsigned long long* s_sorted = s_k3 + CCAP;                   // MAX_DET
        __shared__ int s_res[2];
        __shared__ int s_ncoll;
        __shared__ unsigned s_maxtr;

        if (tid < C_CLS) s_ccnt[tid] = g_keep_count[img * C_CLS + tid];
        if (tid == 0) { s_maxtr = 0; s_ncoll = 0; }
        __syncthreads();
        // largest truncated-away score (lists sorted: element WIN is max beyond window)
        if (tid < C_CLS && s_ccnt[tid] > WIN)
            atomicMax(&s_maxtr, __float_as_uint(g_keep_score[(img * C_CLS + tid) * MAX_DET + WIN]));
        __syncthreads();

        // ---- mode 0: truncated pool (1280), single histogram pass ----
        const int pool0 = C_CLS * WIN;
        for (int i = tid; i < 1024; i += TPB) hist[i] = 0;
        __syncthreads();
        for (int t = tid; t < pool0; t += TPB) {
            int cc = t / WIN, r = t % WIN;
            unsigned u = (r < s_ccnt[cc])
                       ? __float_as_uint(g_keep_score[(img * C_CLS + cc) * MAX_DET + r]) : 0;
            s_u[t] = u;
            if (u) atomicAdd(&hist[u >> 22], 1);
        }
        __syncthreads();
        find_cross(hist, 1024, MAX_DET, tid, wtot, s_res);
        __syncthreads();
        int b1 = s_res[0];
        bool found = (b1 >= 0);

        // collect whole boundary bucket and above (>=300 when found; <=1280 <= CCAP)
        for (int t = tid; t < pool0; t += TPB) {
            unsigned u = s_u[t];
            if (u && (!found || (int)(u >> 22) >= b1)) {
                int pos = atomicAdd(&s_ncoll, 1);
                int cc = t / WIN, r = t % WIN;
                int flat = cc * MAX_DET + r;
                s_k3[pos] = ((unsigned long long)u << 16) | (unsigned)(0xFFFF - flat);
            }
        }
        if (tid < MAX_DET) s_sorted[tid] = 0ull;
        __syncthreads();
        int Ncoll = s_ncoll;

        // rank-scatter: unique keys -> rank = #greater
        for (int i = tid; i < Ncoll; i += TPB) {
            unsigned long long kk = s_k3[i];
            int rank = 0;
            for (int j = 0; j < Ncoll; j++) rank += (s_k3[j] > kk);
            if (rank < MAX_DET) s_sorted[rank] = kk;
        }
        __syncthreads();

        // exact validity: final 300th score strictly above every truncated score
        unsigned u299 = (Ncoll >= MAX_DET) ? (unsigned)(s_sorted[MAX_DET - 1] >> 16) : 0u;
        bool valid = found ? (u299 > s_maxtr) : (s_maxtr == 0);
        __syncthreads();

        if (!valid) {
            // ---- mode 1 (rare): exact 3-pass threshold over full pool ----
            const int pool1 = C_CLS * MAX_DET;
            unsigned Tu = 0;
            for (int i = tid; i < 1024; i += TPB) hist[i] = 0;
            if (tid == 0) s_ncoll = 0;
            __syncthreads();
            for (int t = tid; t < pool1; t += TPB) {
                int cc = t / MAX_DET, r = t % MAX_DET;
                unsigned u = (r < s_ccnt[cc])
                           ? __float_as_uint(g_keep_score[(img * C_CLS + cc) * MAX_DET + r]) : 0;
                if (u) atomicAdd(&hist[u >> 22], 1);
            }
            __syncthreads();
            find_cross(hist, 1024, MAX_DET, tid, wtot, s_res);
            __syncthreads();
            int c1 = s_res[0], na1 = s_res[1];
            found = (c1 >= 0);
            if (found) {
                for (int i = tid; i < NB; i += TPB) hist[i] = 0;
                __syncthreads();
                for (int t = tid; t < pool1; t += TPB) {
                    int cc = t / MAX_DET, r = t % MAX_DET;
                    unsigned u = (r < s_ccnt[cc])
                               ? __float_as_uint(g_keep_score[(img * C_CLS + cc) * MAX_DET + r]) : 0;
                    if (u && (int)(u >> 22) == c1) atomicAdd(&hist[(u >> 11) & 0x7FF], 1);
                }
                __syncthreads();
                find_cross(hist, 2048, MAX_DET - na1, tid, wtot, s_res);
                __syncthreads();
                int c2 = s_res[0], na2 = s_res[1];
                unsigned p2 = ((unsigned)c1 << 11) | (unsigned)c2;

                for (int i = tid; i < NB; i += TPB) hist[i] = 0;
                __syncthreads();
                for (int t = tid; t < pool1; t += TPB) {
                    int cc = t / MAX_DET, r = t % MAX_DET;
                    unsigned u = (r < s_ccnt[cc])
                               ? __float_as_uint(g_keep_score[(img * C_CLS + cc) * MAX_DET + r]) : 0;
                    if (u && (u >> 11) == p2) atomicAdd(&hist[u & 0x7FF], 1);
                }
                __syncthreads();
                find_cross(hist, 2048, MAX_DET - na1 - na2, tid, wtot, s_res);
                __syncthreads();
                Tu = (p2 << 11) | (unsigned)s_res[0];
            }
            __syncthreads();

            for (int t = tid; t < pool1; t += TPB) {
                int cc = t / MAX_DET, r = t % MAX_DET;
                unsigned u = (r < s_ccnt[cc])
                           ? __float_as_uint(g_keep_score[(img * C_CLS + cc) * MAX_DET + r]) : 0;
                if (u && (!found || u >= Tu)) {
                    int pos = atomicAdd(&s_ncoll, 1);
                    if (pos < CCAP) {
                        int flat = cc * MAX_DET + r;
                        s_k3[pos] = ((unsigned long long)u << 16) | (unsigned)(0xFFFF - flat);
                    }
                }
            }
            if (tid < MAX_DET) s_sorted[tid] = 0ull;
            __syncthreads();
            Ncoll = s_ncoll < CCAP ? s_ncoll : CCAP;
            for (int i = tid; i < Ncoll; i += TPB) {
                unsigned long long kk = s_k3[i];
                int rank = 0;
                for (int j = 0; j < Ncoll; j++) rank += (s_k3[j] > kk);
                if (rank < MAX_DET) s_sorted[rank] = kk;
            }
            __syncthreads();
        }

        if (tid < MAX_DET) {
            float* fb = out + img * (MAX_DET * 4) + tid * 4;
            float* fs = out + B_IMG * MAX_DET * 4 + img * MAX_DET + tid;
            float* fl = out + B_IMG * MAX_DET * 4 + B_IMG * MAX_DET + img * MAX_DET + tid;
            unsigned long long kk = s_sorted[tid];
            if (kk != 0ull) {
                unsigned u = (unsigned)(kk >> 16);
                int flat = 0xFFFF - (int)(kk & 0xFFFF);
                int cc = flat / MAX_DET, r = flat % MAX_DET;
                int n = g_keep_idx[(img * C_CLS + cc) * MAX_DET + r];
                float4 bb = reinterpret_cast<const float4*>(boxes)[img * N_BOX + n];
                fb[0] = bb.x; fb[1] = bb.y; fb[2] = bb.z; fb[3] = bb.w;
                *fs = __uint_as_float(u);
                *fl = (float)cc;
            } else {
                fb[0] = -1.0f; fb[1] = -1.0f; fb[2] = -1.0f; fb[3] = -1.0f;
                *fs = -1.0f; *fl = -1.0f;
            }
        }
    }
}

// ---------------- host launcher ----------------
extern "C" void kernel_launch(void* const* d_in, const int* in_sizes, int n_in,
                              void* d_out, int out_size) {
    const float* boxes = (const float*)d_in[0];           // [2,20000,4]
    const float* cls   = (const float*)d_in[1];           // [2,20000,80]
    const float* cen   = (const float*)d_in[2];           // [2,20000,1]
    float* out = (float*)d_out;                           // fb(2400) | fs(600) | fl(600)

    cudaFuncSetAttribute(fused_kernel,
                         cudaFuncAttributeMaxDynamicSharedMemorySize, SMEM_BYTES);

    fused_kernel<<<GRID, TPB, SMEM_BYTES>>>(boxes, (const float4*)cls, cen, out);
}

// round 15
// speedup vs baseline: 1.3447x; 1.3447x over previous
#include <cuda_runtime.h>
#include <float.h>

#define B_IMG 2
#define N_BOX 20000
#define C_CLS 80
#define BC (B_IMG * C_CLS)          // 160
#define CAP 1024                    // global candidate cap per (b,c)
#define CPAD 32                     // counter padding (128B stride)
#define MAXV 512                    // fast-path NMS limit (== TPB); slow fallback beyond
#define WMAX (MAXV / 32)            // 16
#define PRE_K 1000
#define MAX_DET 300
#define SCORE_THR 0.05f
#define IOU_THR 0.5f
#define WIN 32
#define NB 2048
#define CCAP 2048
#define GRID 160
#define TPB 512
#define NWARP (TPB / 32)
#define BATCH 10
#define SMEM_BYTES 67584

// ---------------- scratch (no allocations allowed) ----------------
__device__ int   g_b1, g_done, g_done2;      // barrier + finisher tickets (start 0, self-reset)
__device__ int   g_cand_count[BC * CPAD];
__device__ float g_cand_score[BC * CAP];
__device__ int   g_cand_idx[BC * CAP];
__device__ int   g_keep_count[BC];
__device__ float g_keep_score[BC * MAX_DET];
__device__ int   g_keep_idx[BC * MAX_DET];

// ---- smem bitonic (slow fallback only) ----
__device__ __forceinline__ void bitonic_desc(unsigned long long* sk, int M, int tid) {
    for (int k = 2; k <= M; k <<= 1) {
        for (int j = k >> 1; j > 0; j >>= 1) {
            for (int i = tid; i < M; i += TPB) {
                int ixj = i ^ j;
                if (ixj > i) {
                    unsigned long long a = sk[i], d = sk[ixj];
                    bool up = ((i & k) == 0);
                    if (up ? (a < d) : (a > d)) { sk[i] = d; sk[ixj] = a; }
                }
            }
            __syncthreads();
        }
    }
}

// ---- 2-barrier bucket finder ----
__device__ __forceinline__ void find_cross(const int* hist, int nb, int rem,
                                           int tid, int* warp_tot, int* res) {
    int chunk = nb / TPB;
    int base = tid * chunk;
    int lsum = 0;
    for (int k = 0; k < chunk; k++) lsum += hist[base + k];

    int lane = tid & 31, wid = tid >> 5;
    int suff = lsum;
    #pragma unroll
    for (int off = 1; off < 32; off <<= 1) {
        int v = __shfl_down_sync(0xffffffffu, suff, off);
        if (lane + off < 32) suff += v;
    }
    if (lane == 0) warp_tot[wid] = suff;
    __syncthreads();

    int after_w = 0, total = 0;
    #pragma unroll
    for (int w = 0; w < NWARP; w++) {
        int wt = warp_tot[w];
        total += wt;
        if (w > wid) after_w += wt;
    }
    int incl = after_w + suff;
    int after_c = incl - lsum;
    if (tid == 0 && total < rem) { res[0] = -1; res[1] = total; }
    if (total >= rem && after_c < rem && rem <= incl) {
        int cum = after_c;
        for (int k = chunk - 1; k >= 0; k--) {
            int h = hist[base + k];
            cum += h;
            if (cum >= rem) { res[0] = base + k; res[1] = cum - h; break; }
        }
    }
}

__global__ __launch_bounds__(TPB)
void fused_kernel(const float* __restrict__ boxes,
                  const float4* __restrict__ cls4,
                  const float* __restrict__ cen,
                  float* __restrict__ out) {
    extern __shared__ unsigned char dynbuf[];
    // phase-2 layout
    unsigned long long* s_key  = (unsigned long long*)dynbuf;            // CAP (8KB)
    float4*             s_box  = (float4*)(dynbuf + 8192);               // MAXV (8KB)
    unsigned long long* s_xkey = (unsigned long long*)(dynbuf + 16384);  // MAXV (4KB)
    float*              sx1    = (float*)(dynbuf + 20480);               // MAXV (2KB)
    float4*             s_f4   = (float4*)(dynbuf + 22528);              // MAXV (8KB)
    int*                srank  = (int*)(dynbuf + 30720);                 // MAXV (2KB)
    unsigned*           s_mask = (unsigned*)(dynbuf + 32768);            // MAXV*WMAX (32KB)
    unsigned*           s_anyw = (unsigned*)(dynbuf + 65536);            // WMAX words
    __shared__ int s_ticket;

    const int tid = threadIdx.x;
    const int bc  = blockIdx.x;
    const int b   = bc / C_CLS;

    // ===== phase 1: coalesced threshold + compact (batched loads) =====
    {
        const int total4 = B_IMG * N_BOX * C_CLS / 4;     // 800000
        const int start  = bc * TPB + tid;
        const int stride = GRID * TPB;                    // 81920

        float4 vbuf[BATCH];
        float  cbuf[BATCH];
        #pragma unroll
        for (int k = 0; k < BATCH; k++) {
            int q = start + k * stride;
            if (q < total4) {
                vbuf[k] = cls4[q];
                cbuf[k] = cen[q / 20];    // q/20 == b*N_BOX+n (80%4==0)
            }
        }
        #pragma unroll
        for (int k = 0; k < BATCH; k++) {
            int q = start + k * stride;
            if (q < total4) {
                float4 v = vbuf[k];
                if (v.x > SCORE_THR || v.y > SCORE_THR || v.z > SCORE_THR || v.w > SCORE_THR) {
                    int base = q * 4;
                    int c0  = base % C_CLS;
                    int rem = q / 20;
                    int bb  = rem / N_BOX;
                    float ce = cbuf[k];
                    float vv[4] = {v.x, v.y, v.z, v.w};
                    #pragma unroll
                    for (int e = 0; e < 4; e++) {
                        if (vv[e] > SCORE_THR) {
                            float s = sqrtf(vv[e] * ce);
                            int idx = bb * C_CLS + c0 + e;
                            int pos = atomicAdd(&g_cand_count[idx * CPAD], 1);
                            if (pos < CAP) {
                                g_cand_score[idx * CAP + pos] = s;
                                g_cand_idx[idx * CAP + pos]   = rem % N_BOX;
                            }
                        }
                    }
                }
            }
        }
    }

    // ---- grid barrier 1 ----
    __threadfence();
    __syncthreads();
    if (tid == 0) {
        atomicAdd(&g_b1, 1);
        while (*(volatile int*)&g_b1 < GRID) {}
    }
    __syncthreads();
    __threadfence();

    // ===== phase 2: score rank-sort + x-sweep NMS =====
    int V = g_cand_count[bc * CPAD];
    if (V > CAP) V = CAP;
    {
        int M = 1;
        while (M < V) M <<= 1;

        for (int i = tid; i < M; i += TPB) {
            if (i < V) {
                unsigned sb = __float_as_uint(g_cand_score[bc * CAP + i]);
                unsigned ix = (unsigned)g_cand_idx[bc * CAP + i];
                s_key[i] = ((unsigned long long)sb << 32) | (unsigned)(~ix);
            } else {
                s_key[i] = 0ull;
            }
        }
        __syncthreads();
        if (tid == 0) g_cand_count[bc * CPAD] = 0;   // re-zero for next replay (after sync: safe)

        int K_eff = V < PRE_K ? V : PRE_K;

        if (V <= MAXV) {
            // ---- rank-sort by score key (unique keys), in-place scatter ----
            unsigned long long mykey = (tid < V) ? s_key[tid] : 0ull;
            int rank = 0;
            for (int j = 0; j < V; j++) rank += (s_key[j] > mykey);
            __syncthreads();
            if (tid < V) s_key[rank] = mykey;
            __syncthreads();

            // gather boxes in score order; zero masks
            for (int i = tid; i < V; i += TPB) {
                int n = (int)(~((unsigned)s_key[i]));
                s_box[i] = reinterpret_cast<const float4*>(boxes)[b * N_BOX + n];
            }
            for (int t = tid; t < V * WMAX; t += TPB) s_mask[t] = 0u;
            if (tid < WMAX) s_anyw[tid] = 0u;
            __syncthreads();

            // ---- rank-sort by x1 ascending (key = ~x1bits<<32 | scorerank) ----
            unsigned long long xkey = (tid < V)
                ? ((unsigned long long)(~__float_as_uint(s_box[tid].x)) << 32) | (unsigned)tid
                : 0ull;
            if (tid < V) s_xkey[tid] = xkey;
            __syncthreads();
            int xrank = 0;
            for (int j = 0; j < V; j++) xrank += (s_xkey[j] > xkey);
            __syncthreads();
            if (tid < V) s_xkey[xrank] = xkey;
            __syncthreads();

            // build x-order SoA
            for (int p = tid; p < V; p += TPB) {
                int r = (int)(unsigned)s_xkey[p];
                float4 bb4 = s_box[r];
                sx1[p] = bb4.x;
                s_f4[p] = make_float4(bb4.z, bb4.y, bb4.w,
                                      (bb4.z - bb4.x) * (bb4.w - bb4.y));
                srank[p] = r;
            }
            __syncthreads();

            // pair sweep: q>p overlaps in x iff x1_q < x2_p (x1 ascending)
            for (int p = tid; p < V; p += TPB) {
                float4 fp = s_f4[p];                // (x2, y1, y2, area)
                float x2p = fp.x, y1p = fp.y, y2p = fp.z, arp = fp.w;
                int rp = srank[p];
                for (int q = p + 1; q < V; q++) {
                    float x1q = sx1[q];
                    if (x1q >= x2p) break;
                    float4 fq = s_f4[q];
                    float w_ = fminf(x2p, fq.x) - x1q;
                    float h_ = fminf(y2p, fq.z) - fmaxf(y1p, fq.y);
                    if (h_ > 0.0f) {
                        float inter = w_ * h_;
                        float uni = arp + fq.w - inter;
                        if (inter / fmaxf(uni, 1e-8f) > IOU_THR) {
                            int rq = srank[q];
                            int imin = rp < rq ? rp : rq;
                            int jmax = rp < rq ? rq : rp;
                            atomicOr(&s_mask[imin * WMAX + (jmax >> 5)], 1u << (jmax & 31));
                            atomicOr(&s_anyw[imin >> 5], 1u << (imin & 31));
                        }
                    }
                }
            }
            __syncthreads();

            // chunked serial greedy sweep (warp 0); suppression-sparse fast path
            if (tid < 32) {
                int W = (K_eff + 31) >> 5;
                unsigned sup  = 0;
                unsigned anyw = (tid < WMAX) ? s_anyw[tid] : 0u;
                int nk = 0;
                int nchunk = (K_eff + 31) >> 5;
                for (int g = 0; g < nchunk && nk < MAX_DET; g++) {
                    unsigned ow = __shfl_sync(0xffffffffu, sup,  g);
                    unsigned ag = __shfl_sync(0xffffffffu, anyw, g);
                    int bend = min(32, K_eff - (g << 5));
                    for (int bb2 = 0; bb2 < bend; bb2++) {
                        if (!(ow & (1u << bb2))) {
                            int i = (g << 5) + bb2;
                            if (tid == 0) {
                                unsigned long long kk = s_key[i];
                                g_keep_score[bc * MAX_DET + nk] = __uint_as_float((unsigned)(kk >> 32));
                                g_keep_idx[bc * MAX_DET + nk]   = (int)(~((unsigned)kk));
                            }
                            nk++;
                            if ((ag >> bb2) & 1u) {     // warp-uniform: row i suppresses someone
                                unsigned m = (tid < W) ? s_mask[i * WMAX + tid] : 0u;
                                sup |= m;
                                ow  |= __shfl_sync(0xffffffffu, m, g);
                            }
                            if (nk >= MAX_DET) break;
                        }
                    }
                }
                if (tid == 0) g_keep_count[bc] = nk;
            }
        } else {
            // slow fallback: full bitonic + barrier greedy, boxes from global
            bitonic_desc(s_key, M, tid);
            unsigned char* sup = (unsigned char*)s_mask;
            __shared__ int s_nk;
            for (int i = tid; i < K_eff; i += TPB) sup[i] = 0;
            if (tid == 0) s_nk = 0;
            __syncthreads();
            for (int i = 0; i < K_eff; i++) {
                if (!sup[i]) {
                    unsigned long long ki = s_key[i];
                    int ni = (int)(~((unsigned)ki));
                    if (tid == 0) {
                        int nk = s_nk;
                        g_keep_score[bc * MAX_DET + nk] = __uint_as_float((unsigned)(ki >> 32));
                        g_keep_idx[bc * MAX_DET + nk]   = ni;
                        s_nk = nk + 1;
                    }
                    float4 bi = reinterpret_cast<const float4*>(boxes)[b * N_BOX + ni];
                    float ai = (bi.z - bi.x) * (bi.w - bi.y);
                    for (int j = i + 1 + tid; j < K_eff; j += TPB) {
                        if (!sup[j]) {
                            int nj = (int)(~((unsigned)s_key[j]));
                            float4 bj = reinterpret_cast<const float4*>(boxes)[b * N_BOX + nj];
                            float aj = (bj.z - bj.x) * (bj.w - bj.y);
                            float w_ = fmaxf(fminf(bi.z, bj.z) - fmaxf(bi.x, bj.x), 0.0f);
                            float h_ = fmaxf(fminf(bi.w, bj.w) - fmaxf(bi.y, bj.y), 0.0f);
                            float inter = w_ * h_;
                            float uni = ai + aj - inter;
                            if (inter / fmaxf(uni, 1e-8f) > IOU_THR) sup[j] = 1;
                        }
                    }
                    __syncthreads();
                    if (s_nk >= MAX_DET) break;
                }
            }
            if (tid == 0) g_keep_count[bc] = (s_nk <= MAX_DET) ? s_nk : MAX_DET;
        }
    }

    // ===== finisher ticket: last B_IMG finishers run the merge =====
    __threadfence();
    __syncthreads();
    if (tid == 0) s_ticket = atomicAdd(&g_done, 1);
    __syncthreads();
    int ticket = s_ticket;
    if (ticket < GRID - B_IMG) return;
    const int img = ticket - (GRID - B_IMG);
    if (tid == 0) {
        while (*(volatile int*)&g_done < GRID) {}
        int r = atomicAdd(&g_done2, 1);
        if (r == B_IMG - 1) { g_done = 0; g_done2 = 0; g_b1 = 0; }   // reset for replay
    }
    __syncthreads();
    __threadfence();

    // ===== phase 3: per-image radix-select top-300 (truncated WIN=32 + exact fallback) =====
    {
        unsigned* s_u    = (unsigned*)dynbuf;                         // C_CLS*WIN (10KB)
        int*      hist   = (int*)(s_u + C_CLS * WIN);                 // NB (8KB)
        int*      wtot   = hist + NB;                                 // TPB (2KB; 16 used)
        int*      s_ccnt = wtot + TPB;                                // C_CLS
        unsigned long long* s_k3 = (unsigned long long*)(s_ccnt + C_CLS); // CCAP (16KB)
        unsigned long long* s_sorted = s_k3 + CCAP;                   // MAX_DET
        __shared__ int s_res[2];
        __shared__ int s_ncoll;
        __shared__ unsigned s_maxtr;

        if (tid < C_CLS) s_ccnt[tid] = g_keep_count[img * C_CLS + tid];
        if (tid == 0) { s_maxtr = 0; s_ncoll = 0; }
        __syncthreads();
        if (tid < C_CLS && s_ccnt[tid] > WIN)
            atomicMax(&s_maxtr, __float_as_uint(g_keep_score[(img * C_CLS + tid) * MAX_DET + WIN]));
        __syncthreads();

        unsigned Tu = 0;
        bool found = false;
        int win = WIN, pool = C_CLS * WIN, fmode = 0;

        for (int mode = 0; mode < 2; mode++) {
            win = mode ? MAX_DET : WIN;
            pool = C_CLS * win;
            fmode = mode;

            for (int i = tid; i < 1024; i += TPB) hist[i] = 0;
            __syncthreads();
            for (int t = tid; t < pool; t += TPB) {
                int cc = t / win, r = t % win;
                unsigned u = (r < s_ccnt[cc])
                           ? __float_as_uint(g_keep_score[(img * C_CLS + cc) * MAX_DET + r]) : 0;
                if (!mode) s_u[t] = u;
                if (u) atomicAdd(&hist[u >> 22], 1);
            }
            __syncthreads();
            find_cross(hist, 1024, MAX_DET, tid, wtot, s_res);
            __syncthreads();
            int b1 = s_res[0], na1 = s_res[1];
            found = (b1 >= 0);
            Tu = 0;

            if (found) {
                for (int i = tid; i < NB; i += TPB) hist[i] = 0;
                __syncthreads();
                for (int t = tid; t < pool; t += TPB) {
                    unsigned u;
                    if (!mode) u = s_u[t];
                    else {
                        int cc = t / win, r = t % win;
                        u = (r < s_ccnt[cc])
                          ? __float_as_uint(g_keep_score[(img * C_CLS + cc) * MAX_DET + r]) : 0;
                    }
                    if (u && (int)(u >> 22) == b1) atomicAdd(&hist[(u >> 11) & 0x7FF], 1);
                }
                __syncthreads();
                find_cross(hist, 2048, MAX_DET - na1, tid, wtot, s_res);
                __syncthreads();
                int b2 = s_res[0], na2 = s_res[1];
                unsigned p2 = ((unsigned)b1 << 11) | (unsigned)b2;

                for (int i = tid; i < NB; i += TPB) hist[i] = 0;
                __syncthreads();
                for (int t = tid; t < pool; t += TPB) {
                    unsigned u;
                    if (!mode) u = s_u[t];
                    else {
                        int cc = t / win, r = t % win;
                        u = (r < s_ccnt[cc])
                          ? __float_as_uint(g_keep_score[(img * C_CLS + cc) * MAX_DET + r]) : 0;
                    }
                    if (u && (u >> 11) == p2) atomicAdd(&hist[u & 0x7FF], 1);
                }
                __syncthreads();
                find_cross(hist, 2048, MAX_DET - na1 - na2, tid, wtot, s_res);
                __syncthreads();
                Tu = (p2 << 11) | (unsigned)s_res[0];
            }
            __syncthreads();

            if (mode == 0) {
                bool valid = found ? (Tu > s_maxtr) : (s_maxtr == 0);
                if (valid) break;
            }
        }

        // collect all entries >= exact threshold
        for (int t = tid; t < pool; t += TPB) {
            unsigned u;
            int cc = t / win, r = t % win;
            if (!fmode) u = s_u[t];
            else u = (r < s_ccnt[cc])
                   ? __float_as_uint(g_keep_score[(img * C_CLS + cc) * MAX_DET + r]) : 0;
            if (u && (!found || u >= Tu)) {
                int pos = atomicAdd(&s_ncoll, 1);
                if (pos < CCAP) {
                    int flat = cc * MAX_DET + r;
                    s_k3[pos] = ((unsigned long long)u << 16) | (unsigned)(0xFFFF - flat);
                }
            }
        }
        if (tid < MAX_DET) s_sorted[tid] = 0ull;
        __syncthreads();
        int Ncoll = s_ncoll < CCAP ? s_ncoll : CCAP;

        // rank-scatter: unique keys -> rank = #greater; ranks <300 fill contiguously
        for (int i = tid; i < Ncoll; i += TPB) {
            unsigned long long kk = s_k3[i];
            int rank = 0;
            for (int j = 0; j < Ncoll; j++) rank += (s_k3[j] > kk);
            if (rank < MAX_DET) s_sorted[rank] = kk;
        }
        __syncthreads();

        if (tid < MAX_DET) {
            float* fb = out + img * (MAX_DET * 4) + tid * 4;
            float* fs = out + B_IMG * MAX_DET * 4 + img * MAX_DET + tid;
            float* fl = out + B_IMG * MAX_DET * 4 + B_IMG * MAX_DET + img * MAX_DET + tid;
            unsigned long long kk = s_sorted[tid];
            if (kk != 0ull) {
                unsigned u = (unsigned)(kk >> 16);
                int flat = 0xFFFF - (int)(kk & 0xFFFF);
                int cc = flat / MAX_DET, r = flat % MAX_DET;
                int n = g_keep_idx[(img * C_CLS + cc) * MAX_DET + r];
                float4 bb = reinterpret_cast<const float4*>(boxes)[img * N_BOX + n];
                fb[0] = bb.x; fb[1] = bb.y; fb[2] = bb.z; fb[3] = bb.w;
                *fs = __uint_as_float(u);
                *fl = (float)cc;
            } else {
                fb[0] = -1.0f; fb[1] = -1.0f; fb[2] = -1.0f; fb[3] = -1.0f;
                *fs = -1.0f; *fl = -1.0f;
            }
        }
    }
}

// ---------------- host launcher ----------------
extern "C" void kernel_launch(void* const* d_in, const int* in_sizes, int n_in,
                              void* d_out, int out_size) {
    const float* boxes = (const float*)d_in[0];           // [2,20000,4]
    const float* cls   = (const float*)d_in[1];           // [2,20000,80]
    const float* cen   = (const float*)d_in[2];           // [2,20000,1]
    float* out = (float*)d_out;                           // fb(2400) | fs(600) | fl(600)

    cudaFuncSetAttribute(fused_kernel,
                         cudaFuncAttributeMaxDynamicSharedMemorySize, SMEM_BYTES);

    fused_kernel<<<GRID, TPB, SMEM_BYTES>>>(boxes, (const float4*)cls, cen, out);
}

// round 17
// speedup vs baseline: 1.3898x; 1.0336x over previous
#include <cuda_runtime.h>
#include <float.h>

#define B_IMG 2
#define N_BOX 20000
#define C_CLS 80
#define BC (B_IMG * C_CLS)          // 160
#define CAP 1024                    // global candidate cap per (b,c)
#define CPAD 32                     // counter padding (128B stride)
#define MAXV 512                    // fast-path NMS limit (== TPB); slow fallback beyond
#define WMAX (MAXV / 32)            // 16
#define PRE_K 1000
#define MAX_DET 300
#define SCORE_THR 0.05f
#define IOU_THR 0.5f
#define WIN 32
#define NB 2048
#define PH3_NB 4096                 // range-aware bucket count for 1-pass select
#define BUCK_BASE 0x76C0            // (u>>15) lower bound for comb scores (~0.0055)
#define CCAP 2048
#define GRID 160
#define TPB 512
#define NWARP (TPB / 32)
#define BATCH 10
#define SMEM_BYTES 67584

// ---------------- scratch (no allocations allowed) ----------------
__device__ int   g_b1, g_done, g_done2;      // barrier + finisher tickets (start 0, self-reset)
__device__ int   g_cand_count[BC * CPAD];
__device__ float g_cand_score[BC * CAP];
__device__ int   g_cand_idx[BC * CAP];
__device__ int   g_keep_count[BC];
__device__ float g_keep_score[BC * MAX_DET];
__device__ int   g_keep_idx[BC * MAX_DET];

// monotone bucket function over the known score range
__device__ __forceinline__ int ph3_bucket(unsigned u) {
    int bkt = (int)(u >> 15) - BUCK_BASE;
    if (bkt < 0) bkt = 0;
    if (bkt > PH3_NB - 1) bkt = PH3_NB - 1;
    return bkt;
}

// ---- smem bitonic (slow fallback only) ----
__device__ __forceinline__ void bitonic_desc(unsigned long long* sk, int M, int tid) {
    for (int k = 2; k <= M; k <<= 1) {
        for (int j = k >> 1; j > 0; j >>= 1) {
            for (int i = tid; i < M; i += TPB) {
                int ixj = i ^ j;
                if (ixj > i) {
                    unsigned long long a = sk[i], d = sk[ixj];
                    bool up = ((i & k) == 0);
                    if (up ? (a < d) : (a > d)) { sk[i] = d; sk[ixj] = a; }
                }
            }
            __syncthreads();
        }
    }
}

// ---- 2-barrier bucket finder ----
__device__ __forceinline__ void find_cross(const int* hist, int nb, int rem,
                                           int tid, int* warp_tot, int* res) {
    int chunk = nb / TPB;
    int base = tid * chunk;
    int lsum = 0;
    for (int k = 0; k < chunk; k++) lsum += hist[base + k];

    int lane = tid & 31, wid = tid >> 5;
    int suff = lsum;
    #pragma unroll
    for (int off = 1; off < 32; off <<= 1) {
        int v = __shfl_down_sync(0xffffffffu, suff, off);
        if (lane + off < 32) suff += v;
    }
    if (lane == 0) warp_tot[wid] = suff;
    __syncthreads();

    int after_w = 0, total = 0;
    #pragma unroll
    for (int w = 0; w < NWARP; w++) {
        int wt = warp_tot[w];
        total += wt;
        if (w > wid) after_w += wt;
    }
    int incl = after_w + suff;
    int after_c = incl - lsum;
    if (tid == 0 && total < rem) { res[0] = -1; res[1] = total; }
    if (total >= rem && after_c < rem && rem <= incl) {
        int cum = after_c;
        for (int k = chunk - 1; k >= 0; k--) {
            int h = hist[base + k];
            cum += h;
            if (cum >= rem) { res[0] = base + k; res[1] = cum - h; break; }
        }
    }
}

__global__ __launch_bounds__(TPB)
void fused_kernel(const float* __restrict__ boxes,
                  const float4* __restrict__ cls4,
                  const float* __restrict__ cen,
                  float* __restrict__ out) {
    extern __shared__ unsigned char dynbuf[];
    // phase-2 layout
    unsigned long long* s_key  = (unsigned long long*)dynbuf;            // CAP (8KB)
    float4*             s_box  = (float4*)(dynbuf + 8192);               // MAXV (8KB)
    unsigned long long* s_xkey = (unsigned long long*)(dynbuf + 16384);  // MAXV (4KB)
    float*              sx1    = (float*)(dynbuf + 20480);               // MAXV (2KB)
    float4*             s_f4   = (float4*)(dynbuf + 22528);              // MAXV (8KB)
    int*                srank  = (int*)(dynbuf + 30720);                 // MAXV (2KB)
    unsigned*           s_mask = (unsigned*)(dynbuf + 32768);            // MAXV*WMAX (32KB)
    unsigned*           s_anyw = (unsigned*)(dynbuf + 65536);            // WMAX words
    __shared__ int s_ticket;

    const int tid = threadIdx.x;
    const int bc  = blockIdx.x;
    const int b   = bc / C_CLS;

    // ===== phase 1: coalesced threshold + compact (batched loads) =====
    {
        const int total4 = B_IMG * N_BOX * C_CLS / 4;     // 800000
        const int start  = bc * TPB + tid;
        const int stride = GRID * TPB;                    // 81920

        float4 vbuf[BATCH];
        float  cbuf[BATCH];
        #pragma unroll
        for (int k = 0; k < BATCH; k++) {
            int q = start + k * stride;
            if (q < total4) {
                vbuf[k] = cls4[q];
                cbuf[k] = cen[q / 20];    // q/20 == b*N_BOX+n (80%4==0)
            }
        }
        #pragma unroll
        for (int k = 0; k < BATCH; k++) {
            int q = start + k * stride;
            if (q < total4) {
                float4 v = vbuf[k];
                if (v.x > SCORE_THR || v.y > SCORE_THR || v.z > SCORE_THR || v.w > SCORE_THR) {
                    int base = q * 4;
                    int c0  = base % C_CLS;
                    int rem = q / 20;
                    int bb  = rem / N_BOX;
                    float ce = cbuf[k];
                    float vv[4] = {v.x, v.y, v.z, v.w};
                    #pragma unroll
                    for (int e = 0; e < 4; e++) {
                        if (vv[e] > SCORE_THR) {
                            float s = sqrtf(vv[e] * ce);
                            int idx = bb * C_CLS + c0 + e;
                            int pos = atomicAdd(&g_cand_count[idx * CPAD], 1);
                            if (pos < CAP) {
                                g_cand_score[idx * CAP + pos] = s;
                                g_cand_idx[idx * CAP + pos]   = rem % N_BOX;
                            }
                        }
                    }
                }
            }
        }
    }

    // ---- grid barrier 1 ----
    __threadfence();
    __syncthreads();
    if (tid == 0) {
        atomicAdd(&g_b1, 1);
        while (*(volatile int*)&g_b1 < GRID) {}
    }
    __syncthreads();
    __threadfence();

    // ===== phase 2: score rank-sort + x-sweep NMS =====
    int V = g_cand_count[bc * CPAD];
    if (V > CAP) V = CAP;
    {
        int M = 1;
        while (M < V) M <<= 1;

        for (int i = tid; i < M; i += TPB) {
            if (i < V) {
                unsigned sb = __float_as_uint(g_cand_score[bc * CAP + i]);
                unsigned ix = (unsigned)g_cand_idx[bc * CAP + i];
                s_key[i] = ((unsigned long long)sb << 32) | (unsigned)(~ix);
            } else {
                s_key[i] = 0ull;
            }
        }
        __syncthreads();
        if (tid == 0) g_cand_count[bc * CPAD] = 0;   // re-zero for next replay (after sync: safe)

        int K_eff = V < PRE_K ? V : PRE_K;

        if (V <= MAXV) {
            // ---- rank-sort by score key (unique keys), in-place scatter ----
            unsigned long long mykey = (tid < V) ? s_key[tid] : 0ull;
            int rank = 0;
            for (int j = 0; j < V; j++) rank += (s_key[j] > mykey);
            __syncthreads();
            if (tid < V) s_key[rank] = mykey;
            __syncthreads();

            // gather boxes in score order; zero masks
            for (int i = tid; i < V; i += TPB) {
                int n = (int)(~((unsigned)s_key[i]));
                s_box[i] = reinterpret_cast<const float4*>(boxes)[b * N_BOX + n];
            }
            for (int t = tid; t < V * WMAX; t += TPB) s_mask[t] = 0u;
            if (tid < WMAX) s_anyw[tid] = 0u;
            __syncthreads();

            // ---- rank-sort by x1 ascending (key = ~x1bits<<32 | scorerank) ----
            unsigned long long xkey = (tid < V)
                ? ((unsigned long long)(~__float_as_uint(s_box[tid].x)) << 32) | (unsigned)tid
                : 0ull;
            if (tid < V) s_xkey[tid] = xkey;
            __syncthreads();
            int xrank = 0;
            for (int j = 0; j < V; j++) xrank += (s_xkey[j] > xkey);
            __syncthreads();
            if (tid < V) s_xkey[xrank] = xkey;
            __syncthreads();

            // build x-order SoA
            for (int p = tid; p < V; p += TPB) {
                int r = (int)(unsigned)s_xkey[p];
                float4 bb4 = s_box[r];
                sx1[p] = bb4.x;
                s_f4[p] = make_float4(bb4.z, bb4.y, bb4.w,
                                      (bb4.z - bb4.x) * (bb4.w - bb4.y));
                srank[p] = r;
            }
            __syncthreads();

            // pair sweep: q>p overlaps in x iff x1_q < x2_p (x1 ascending)
            for (int p = tid; p < V; p += TPB) {
                float4 fp = s_f4[p];                // (x2, y1, y2, area)
                float x2p = fp.x, y1p = fp.y, y2p = fp.z, arp = fp.w;
                int rp = srank[p];
                for (int q = p + 1; q < V; q++) {
                    float x1q = sx1[q];
                    if (x1q >= x2p) break;
                    float4 fq = s_f4[q];
                    float w_ = fminf(x2p, fq.x) - x1q;
                    float h_ = fminf(y2p, fq.z) - fmaxf(y1p, fq.y);
                    if (h_ > 0.0f) {
                        float inter = w_ * h_;
                        float uni = arp + fq.w - inter;
                        if (inter / fmaxf(uni, 1e-8f) > IOU_THR) {
                            int rq = srank[q];
                            int imin = rp < rq ? rp : rq;
                            int jmax = rp < rq ? rq : rp;
                            atomicOr(&s_mask[imin * WMAX + (jmax >> 5)], 1u << (jmax & 31));
                            atomicOr(&s_anyw[imin >> 5], 1u << (imin & 31));
                        }
                    }
                }
            }
            __syncthreads();

            // chunked serial greedy sweep (warp 0); suppression-sparse fast path
            if (tid < 32) {
                int W = (K_eff + 31) >> 5;
                unsigned sup  = 0;
                unsigned anyw = (tid < WMAX) ? s_anyw[tid] : 0u;
                int nk = 0;
                int nchunk = (K_eff + 31) >> 5;
                for (int g = 0; g < nchunk && nk < MAX_DET; g++) {
                    unsigned ow = __shfl_sync(0xffffffffu, sup,  g);
                    unsigned ag = __shfl_sync(0xffffffffu, anyw, g);
                    int bend = min(32, K_eff - (g << 5));
                    for (int bb2 = 0; bb2 < bend; bb2++) {
                        if (!(ow & (1u << bb2))) {
                            int i = (g << 5) + bb2;
                            if (tid == 0) {
                                unsigned long long kk = s_key[i];
                                g_keep_score[bc * MAX_DET + nk] = __uint_as_float((unsigned)(kk >> 32));
                                g_keep_idx[bc * MAX_DET + nk]   = (int)(~((unsigned)kk));
                            }
                            nk++;
                            if ((ag >> bb2) & 1u) {     // warp-uniform: row i suppresses someone
                                unsigned m = (tid < W) ? s_mask[i * WMAX + tid] : 0u;
                                sup |= m;
                                ow  |= __shfl_sync(0xffffffffu, m, g);
                            }
                            if (nk >= MAX_DET) break;
                        }
                    }
                }
                if (tid == 0) g_keep_count[bc] = nk;
            }
        } else {
            // slow fallback: full bitonic + barrier greedy, boxes from global
            bitonic_desc(s_key, M, tid);
            unsigned char* sup = (unsigned char*)s_mask;
            __shared__ int s_nk;
            for (int i = tid; i < K_eff; i += TPB) sup[i] = 0;
            if (tid == 0) s_nk = 0;
            __syncthreads();
            for (int i = 0; i < K_eff; i++) {
                if (!sup[i]) {
                    unsigned long long ki = s_key[i];
                    int ni = (int)(~((unsigned)ki));
                    if (tid == 0) {
                        int nk = s_nk;
                        g_keep_score[bc * MAX_DET + nk] = __uint_as_float((unsigned)(ki >> 32));
                        g_keep_idx[bc * MAX_DET + nk]   = ni;
                        s_nk = nk + 1;
                    }
                    float4 bi = reinterpret_cast<const float4*>(boxes)[b * N_BOX + ni];
                    float ai = (bi.z - bi.x) * (bi.w - bi.y);
                    for (int j = i + 1 + tid; j < K_eff; j += TPB) {
                        if (!sup[j]) {
                            int nj = (int)(~((unsigned)s_key[j]));
                            float4 bj = reinterpret_cast<const float4*>(boxes)[b * N_BOX + nj];
                            float aj = (bj.z - bj.x) * (bj.w - bj.y);
                            float w_ = fmaxf(fminf(bi.z, bj.z) - fmaxf(bi.x, bj.x), 0.0f);
                            float h_ = fmaxf(fminf(bi.w, bj.w) - fmaxf(bi.y, bj.y), 0.0f);
                            float inter = w_ * h_;
                            float uni = ai + aj - inter;
                            if (inter / fmaxf(uni, 1e-8f) > IOU_THR) sup[j] = 1;
                        }
                    }
                    __syncthreads();
                    if (s_nk >= MAX_DET) break;
                }
            }
            if (tid == 0) g_keep_count[bc] = (s_nk <= MAX_DET) ? s_nk : MAX_DET;
        }
    }

    // ===== finisher ticket: last B_IMG finishers run the merge =====
    __threadfence();
    __syncthreads();
    if (tid == 0) s_ticket = atomicAdd(&g_done, 1);
    __syncthreads();
    int ticket = s_ticket;
    if (ticket < GRID - B_IMG) return;
    const int img = ticket - (GRID - B_IMG);
    if (tid == 0) {
        while (*(volatile int*)&g_done < GRID) {}
        int r = atomicAdd(&g_done2, 1);
        if (r == B_IMG - 1) { g_done = 0; g_done2 = 0; g_b1 = 0; }   // reset for replay
    }
    __syncthreads();
    __threadfence();

    // ===== phase 3: per-image top-300, WIN=32 truncated, 1-pass range-aware select =====
    {
        unsigned* s_u    = (unsigned*)dynbuf;                         // C_CLS*WIN (10240 B)
        int*      hist   = (int*)(s_u + C_CLS * WIN);                 // PH3_NB (16384 B)
        int*      wtot   = hist + PH3_NB;                             // 64 ints
        int*      s_ccnt = wtot + 64;                                 // C_CLS
        unsigned long long* s_k3 = (unsigned long long*)(s_ccnt + C_CLS); // CCAP (16384 B)
        unsigned long long* s_sorted = s_k3 + CCAP;                   // MAX_DET
        __shared__ int s_res[2];
        __shared__ int s_ncoll;
        __shared__ unsigned s_maxtr;

        if (tid < C_CLS) s_ccnt[tid] = g_keep_count[img * C_CLS + tid];
        if (tid == 0) { s_maxtr = 0; s_ncoll = 0; }
        __syncthreads();
        // largest truncated-away score (lists sorted: element WIN is max beyond window)
        if (tid < C_CLS && s_ccnt[tid] > WIN)
            atomicMax(&s_maxtr, __float_as_uint(g_keep_score[(img * C_CLS + tid) * MAX_DET + WIN]));
        __syncthreads();

        // ---- mode 0: truncated pool, ONE histogram pass (mantissa-resolution buckets) ----
        const int pool0 = C_CLS * WIN;
        for (int i = tid; i < PH3_NB; i += TPB) hist[i] = 0;
        __syncthreads();
        for (int t = tid; t < pool0; t += TPB) {
            int cc = t / WIN, r = t % WIN;
            unsigned u = (r < s_ccnt[cc])
                       ? __float_as_uint(g_keep_score[(img * C_CLS + cc) * MAX_DET + r]) : 0;
            s_u[t] = u;
            if (u) atomicAdd(&hist[ph3_bucket(u)], 1);
        }
        __syncthreads();
        find_cross(hist, PH3_NB, MAX_DET, tid, wtot, s_res);
        __syncthreads();
        int b1 = s_res[0];
        bool found = (b1 >= 0);

        // collect boundary bucket and above (tight: ~300 + few entries)
        for (int t = tid; t < pool0; t += TPB) {
            unsigned u = s_u[t];
            if (u && (!found || ph3_bucket(u) >= b1)) {
                int pos = atomicAdd(&s_ncoll, 1);
                if (pos < CCAP) {
                    int cc = t / WIN, r = t % WIN;
                    int flat = cc * MAX_DET + r;
                    s_k3[pos] = ((unsigned long long)u << 16) | (unsigned)(0xFFFF - flat);
                }
            }
        }
        if (tid < MAX_DET) s_sorted[tid] = 0ull;
        __syncthreads();
        int NcollRaw = s_ncoll;
        int Ncoll = NcollRaw < CCAP ? NcollRaw : CCAP;

        // rank-scatter: unique keys -> rank = #greater
        for (int i = tid; i < Ncoll; i += TPB) {
            unsigned long long kk = s_k3[i];
            int rank = 0;
            for (int j = 0; j < Ncoll; j++) rank += (s_k3[j] > kk);
            if (rank < MAX_DET) s_sorted[rank] = kk;
        }
        __syncthreads();

        // exact validity: no collection overflow AND final 300th score strictly above
        // every truncated score (strict tie -> fallback)
        unsigned u299 = (Ncoll >= MAX_DET) ? (unsigned)(s_sorted[MAX_DET - 1] >> 16) : 0u;
        bool valid = found ? (NcollRaw <= CCAP && u299 > s_maxtr) : (s_maxtr == 0);
        __syncthreads();

        if (!valid) {
            // ---- mode 1 (rare): exact 3-pass threshold over full untruncated pool ----
            const int pool1 = C_CLS * MAX_DET;
            unsigned Tu = 0;
            for (int i = tid; i < 1024; i += TPB) hist[i] = 0;
            if (tid == 0) s_ncoll = 0;
            __syncthreads();
            for (int t = tid; t < pool1; t += TPB) {
                int cc = t / MAX_DET, r = t % MAX_DET;
                unsigned u = (r < s_ccnt[cc])
                           ? __float_as_uint(g_keep_score[(img * C_CLS + cc) * MAX_DET + r]) : 0;
                if (u) atomicAdd(&hist[u >> 22], 1);
            }
            __syncthreads();
            find_cross(hist, 1024, MAX_DET, tid, wtot, s_res);
            __syncthreads();
            int c1 = s_res[0], na1 = s_res[1];
            found = (c1 >= 0);
            if (found) {
                for (int i = tid; i < NB; i += TPB) hist[i] = 0;
                __syncthreads();
                for (int t = tid; t < pool1; t += TPB) {
                    int cc = t / MAX_DET, r = t % MAX_DET;
                    unsigned u = (r < s_ccnt[cc])
                               ? __float_as_uint(g_keep_score[(img * C_CLS + cc) * MAX_DET + r]) : 0;
                    if (u && (int)(u >> 22) == c1) atomicAdd(&hist[(u >> 11) & 0x7FF], 1);
                }
                __syncthreads();
                find_cross(hist, 2048, MAX_DET - na1, tid, wtot, s_res);
                __syncthreads();
                int c2 = s_res[0], na2 = s_res[1];
                unsigned p2 = ((unsigned)c1 << 11) | (unsigned)c2;

                for (int i = tid; i < NB; i += TPB) hist[i] = 0;
                __syncthreads();
                for (int t = tid; t < pool1; t += TPB) {
                    int cc = t / MAX_DET, r = t % MAX_DET;
                    unsigned u = (r < s_ccnt[cc])
                               ? __float_as_uint(g_keep_score[(img * C_CLS + cc) * MAX_DET + r]) : 0;
                    if (u && (u >> 11) == p2) atomicAdd(&hist[u & 0x7FF], 1);
                }
                __syncthreads();
                find_cross(hist, 2048, MAX_DET - na1 - na2, tid, wtot, s_res);
                __syncthreads();
                Tu = (p2 << 11) | (unsigned)s_res[0];
            }
            __syncthreads();

            for (int t = tid; t < pool1; t += TPB) {
                int cc = t / MAX_DET, r = t % MAX_DET;
                unsigned u = (r < s_ccnt[cc])
                           ? __float_as_uint(g_keep_score[(img * C_CLS + cc) * MAX_DET + r]) : 0;
                if (u && (!found || u >= Tu)) {
                    int pos = atomicAdd(&s_ncoll, 1);
                    if (pos < CCAP) {
                        int flat = cc * MAX_DET + r;
                        s_k3[pos] = ((unsigned long long)u << 16) | (unsigned)(0xFFFF - flat);
                    }
                }
            }
            if (tid < MAX_DET) s_sorted[tid] = 0ull;
            __syncthreads();
            Ncoll = s_ncoll < CCAP ? s_ncoll : CCAP;
            for (int i = tid; i < Ncoll; i += TPB) {
                unsigned long long kk = s_k3[i];
                int rank = 0;
                for (int j = 0; j < Ncoll; j++) rank += (s_k3[j] > kk);
                if (rank < MAX_DET) s_sorted[rank] = kk;
            }
            __syncthreads();
        }

        if (tid < MAX_DET) {
            float* fb = out + img * (MAX_DET * 4) + tid * 4;
            float* fs = out + B_IMG * MAX_DET * 4 + img * MAX_DET + tid;
            float* fl = out + B_IMG * MAX_DET * 4 + B_IMG * MAX_DET + img * MAX_DET + tid;
            unsigned long long kk = s_sorted[tid];
            if (kk != 0ull) {
                unsigned u = (unsigned)(kk >> 16);
                int flat = 0xFFFF - (int)(kk & 0xFFFF);
                int cc = flat / MAX_DET, r = flat % MAX_DET;
                int n = g_keep_idx[(img * C_CLS + cc) * MAX_DET + r];
                float4 bb = reinterpret_cast<const float4*>(boxes)[img * N_BOX + n];
                fb[0] = bb.x; fb[1] = bb.y; fb[2] = bb.z; fb[3] = bb.w;
                *fs = __uint_as_float(u);
                *fl = (float)cc;
            } else {
                fb[0] = -1.0f; fb[1] = -1.0f; fb[2] = -1.0f; fb[3] = -1.0f;
                *fs = -1.0f; *fl = -1.0f;
            }
        }
    }
}

// ---------------- host launcher ----------------
extern "C" void kernel_launch(void* const* d_in, const int* in_sizes, int n_in,
                              void* d_out, int out_size) {
    const float* boxes = (const float*)d_in[0];           // [2,20000,4]
    const float* cls   = (const float*)d_in[1];           // [2,20000,80]
    const float* cen   = (const float*)d_in[2];           // [2,20000,1]
    float* out = (float*)d_out;                           // fb(2400) | fs(600) | fl(600)

    cudaFuncSetAttribute(fused_kernel,
                         cudaFuncAttributeMaxDynamicSharedMemorySize, SMEM_BYTES);

    fused_kernel<<<GRID, TPB, SMEM_BYTES>>>(boxes, (const float4*)cls, cen, out);
}